// round 11
// baseline (speedup 1.0000x reference)
#include <cuda_runtime.h>
#include <math.h>

#define NTILES   444
#define S1_SPLIT 4
#define S1_THREADS 256
#define CHUNK    256
#define S2_THREADS 320                    // warp0 consumer, 1..8 emb prod, 9 x prod
#define TPL 14                            // ceil(444/32) tiles per lane in scan

// scratch (no device allocations allowed)
__device__ double g_part[NTILES][S1_SPLIT][32];  // stage1 partial sums
__device__ float  g_sstar[NTILES][32];           // fp32 chain start per tile
__device__ double g_cdelta[NTILES][32];          // replayed fp32 tile delta
__device__ unsigned int g_cnt1 = 0;              // last-block counters
__device__ unsigned int g_cnt2 = 0;

// ---- stage 1: float4-coalesced fp32 tile sums + fused prefix scan ----
__global__ void __launch_bounds__(S1_THREADS)
stage1_kernel(const float* __restrict__ x, const float* __restrict__ emb,
              int F, int tilef) {
    __shared__ float sred[8][32];
    __shared__ unsigned int s_last;
    const int tile = blockIdx.x / S1_SPLIT;
    const int part = blockIdx.x % S1_SPLIT;
    const int tid = threadIdx.x, lane = tid & 31, warp = tid >> 5;

    const int base = tile * tilef;
    const int len = min(tilef, F - base);
    const int plen = (len + S1_SPLIT - 1) / S1_SPLIT;       // rows per part
    const int rbeg = part * plen;
    const int rend = min(len, rbeg + plen);
    const int jbeg = rbeg * 4, jend = rend * 4;             // float4 index range

    float ae0 = 0.f, ae1 = 0.f, ae2 = 0.f, ae3 = 0.f;
    float as0 = 0.f, as1 = 0.f, as2 = 0.f, as3 = 0.f;
    const float4* __restrict__ emb4 = (const float4*)(emb + (size_t)base * 16);

    // 4-wide batched loads for MLP; stride 1024 keeps column group (tid&3) fixed
    for (int j0 = jbeg + tid; j0 < jend; j0 += S1_THREADS * 4) {
        float4 v[4]; float xv[4];
        #pragma unroll
        for (int k = 0; k < 4; k++) {
            int j = j0 + k * S1_THREADS;
            if (j < jend) { v[k] = __ldg(emb4 + j); xv[k] = __ldg(x + base + (j >> 2)); }
            else { v[k] = make_float4(0.f,0.f,0.f,0.f); xv[k] = 0.f; }
        }
        #pragma unroll
        for (int k = 0; k < 4; k++) {
            float x2 = xv[k] * xv[k];
            ae0 = __fmaf_rn(v[k].x, xv[k], ae0);
            ae1 = __fmaf_rn(v[k].y, xv[k], ae1);
            ae2 = __fmaf_rn(v[k].z, xv[k], ae2);
            ae3 = __fmaf_rn(v[k].w, xv[k], ae3);
            as0 = __fmaf_rn(v[k].x * v[k].x, x2, as0);
            as1 = __fmaf_rn(v[k].y * v[k].y, x2, as1);
            as2 = __fmaf_rn(v[k].z * v[k].z, x2, as2);
            as3 = __fmaf_rn(v[k].w * v[k].w, x2, as3);
        }
    }

    #pragma unroll
    for (int off = 16; off >= 4; off >>= 1) {
        ae0 += __shfl_down_sync(0xffffffffu, ae0, off);
        ae1 += __shfl_down_sync(0xffffffffu, ae1, off);
        ae2 += __shfl_down_sync(0xffffffffu, ae2, off);
        ae3 += __shfl_down_sync(0xffffffffu, ae3, off);
        as0 += __shfl_down_sync(0xffffffffu, as0, off);
        as1 += __shfl_down_sync(0xffffffffu, as1, off);
        as2 += __shfl_down_sync(0xffffffffu, as2, off);
        as3 += __shfl_down_sync(0xffffffffu, as3, off);
    }
    if (lane < 4) {
        int c0 = lane * 4;
        sred[warp][c0 + 0] = ae0;  sred[warp][c0 + 1] = ae1;
        sred[warp][c0 + 2] = ae2;  sred[warp][c0 + 3] = ae3;
        sred[warp][16 + c0 + 0] = as0;  sred[warp][16 + c0 + 1] = as1;
        sred[warp][16 + c0 + 2] = as2;  sred[warp][16 + c0 + 3] = as3;
    }
    __syncthreads();
    if (warp == 0) {
        double s = 0;
        #pragma unroll
        for (int w = 0; w < 8; w++) s += (double)sred[w][lane];
        g_part[tile][part][lane] = s;
    }

    // ---- last block: exclusive prefix scan over tiles ----
    __syncthreads();
    if (tid == 0) {
        __threadfence();
        unsigned int r = atomicAdd(&g_cnt1, 1u);
        s_last = (r == (unsigned)gridDim.x - 1u) ? 1u : 0u;
    }
    __syncthreads();
    if (!s_last) return;
    __threadfence();

    // 8 warps; warp w scans chains w, w+8, w+16, w+24.
    #pragma unroll
    for (int q = 0; q < 4; q++) {
        const int c = warp + 8 * q;
        double loc[TPL];
        double tot = 0.0;
        #pragma unroll
        for (int j = 0; j < TPL; j++) {
            int t = lane * TPL + j;
            double s = 0.0;
            if (t < NTILES) {
                #pragma unroll
                for (int p = 0; p < S1_SPLIT; p++) s += g_part[t][p][c];
            }
            loc[j] = s;
            tot += s;
        }
        double scan = tot;
        #pragma unroll
        for (int off = 1; off < 32; off <<= 1) {
            double v = __shfl_up_sync(0xffffffffu, scan, off);
            if (lane >= off) scan += v;
        }
        double P = scan - tot;
        #pragma unroll
        for (int j = 0; j < TPL; j++) {
            int t = lane * TPL + j;
            if (t < NTILES) g_sstar[t][c] = (float)P;
            P += loc[j];
        }
    }
    if (tid == 0) g_cnt1 = 0;
}

// ---- stage 2: replay each tile's fp32 chain + fused tail/MLP ----
__global__ void __launch_bounds__(S2_THREADS, 3)
stage2_kernel(const float* __restrict__ x, const float* __restrict__ emb,
              int F, int tilef,
              const float* __restrict__ w_log, const float* __restrict__ b_log,
              const float* __restrict__ w1,    const float* __restrict__ b1,
              const float* __restrict__ w2,    const float* __restrict__ b2,
              const float* __restrict__ w_out, const float* __restrict__ b_out,
              float* __restrict__ out) {
    extern __shared__ float smem_raw[];
    float*  s_a = smem_raw;                              // [2][CHUNK][16] raw tile copy
    float2* s_x = (float2*)(smem_raw + 2 * CHUNK * 16);  // [2][CHUNK]
    __shared__ unsigned int s_last;
    __shared__ double sred2[32][8];
    __shared__ float s_acc[32];
    __shared__ float s_h1[32];

    const int tile = blockIdx.x;
    const int tid = threadIdx.x, lane = tid & 31, warp = tid >> 5;
    const int base = tile * tilef;
    const int len = min(tilef, F - base);
    const int nchunk = (len + CHUNK - 1) / CHUNK;
    const bool lo = lane < 16;
    const int e = lane & 15;

    auto fill = [&](int c) {
        const int cbase = c * CHUNK;
        const int cnt = min(CHUNK, len - cbase);
        const int buf = c & 1;
        if (warp >= 1 && warp <= 8) {
            // raw copy: task t moves float4 t of the chunk's 64B-row block
            float4* sa4 = (float4*)(s_a + buf * (CHUNK * 16));
            const float4* __restrict__ emb4 =
                (const float4*)(emb + (size_t)(base + cbase) * 16);
            const int pt = (warp - 1) * 32 + lane;
            const int ntask = cnt * 4;
            float4 v[4];
            #pragma unroll
            for (int k = 0; k < 4; k++) {
                int task = pt + k * 256;
                if (task < ntask) v[k] = __ldg(emb4 + task);
            }
            #pragma unroll
            for (int k = 0; k < 4; k++) {
                int task = pt + k * 256;
                if (task < ntask) sa4[task] = v[k];
            }
        } else if (warp == 9) {
            float2* sx = s_x + buf * CHUNK;
            #pragma unroll
            for (int k = 0; k < CHUNK / 32; k++) {
                int i = lane + k * 32;
                if (i < cnt) {
                    float xv = __ldg(x + base + cbase + i);
                    sx[i] = make_float2(xv, __fmul_rn(xv, xv));
                }
            }
        }
    };

    if (warp > 0) fill(0);
    __syncthreads();

    float acc = g_sstar[tile][lane];

    for (int c = 0; c < nchunk; c++) {
        if (warp == 0) {
            // consumer: strictly sequential fp32 FMA chain, f ascending
            const float*  sa = s_a + (c & 1) * (CHUNK * 16) + e;
            const float2* sx = s_x + (c & 1) * CHUNK;
            const int cnt = min(CHUNK, len - c * CHUNK);
            if (cnt == CHUNK) {
                #pragma unroll 16
                for (int i = 0; i < CHUNK; i++) {
                    float v = sa[i * 16];
                    float2 xx = sx[i];
                    float a = lo ? v : __fmul_rn(v, v);
                    float b = lo ? xx.x : xx.y;
                    acc = __fmaf_rn(a, b, acc);
                }
            } else {
                for (int i = 0; i < cnt; i++) {
                    float v = sa[i * 16];
                    float2 xx = sx[i];
                    float a = lo ? v : __fmul_rn(v, v);
                    float b = lo ? xx.x : xx.y;
                    acc = __fmaf_rn(a, b, acc);
                }
            }
        } else if (c + 1 < nchunk) {
            fill(c + 1);
        }
        __syncthreads();
    }

    if (warp == 0)
        g_cdelta[tile][lane] = (double)acc - (double)g_sstar[tile][lane];

    // ---- last block: delta reduction + MLP tail ----
    __syncthreads();
    if (tid == 0) {
        __threadfence();
        unsigned int r = atomicAdd(&g_cnt2, 1u);
        s_last = (r == (unsigned)gridDim.x - 1u) ? 1u : 0u;
    }
    __syncthreads();
    if (!s_last) return;
    __threadfence();

    if (tid < 256) {
        const int c = tid >> 3, j = tid & 7;
        double S0 = 0.0, S1 = 0.0;
        for (int t = j; t < NTILES; t += 16) S0 += g_cdelta[t][c];
        for (int t = j + 8; t < NTILES; t += 16) S1 += g_cdelta[t][c];
        sred2[c][j] = S0 + S1;
    }
    __syncthreads();
    if (tid < 32) {
        double S = 0.0;
        #pragma unroll
        for (int j = 0; j < 8; j++) S += sred2[tid][j];
        s_acc[tid] = (float)S;
    }
    __syncthreads();

    if (tid < 32) {
        const int t = tid;
        float h1 = b1[t];
        #pragma unroll
        for (int k = 0; k < 16; k++) h1 = fmaf(s_acc[k], w1[t * 16 + k], h1);
        h1 = fmaxf(h1, 0.0f);
        s_h1[t] = h1;
        __syncwarp();

        float h2 = b2[t];
        #pragma unroll
        for (int k = 0; k < 32; k++) h2 = fmaf(s_h1[k], w2[t * 32 + k], h2);
        h2 = fmaxf(h2, 0.0f);

        float part = h2 * w_out[t];
        if (t < 16) {
            float ef = s_acc[t];
            float fm = 0.5f * (ef * ef - s_acc[16 + t]);
            part = fmaf(fm, w_out[32 + t], part);
        }
        if (t == 0) {
            float logit = b_log[0];
            #pragma unroll
            for (int k = 0; k < 16; k++) logit = fmaf(s_acc[k], w_log[k], logit);
            part = fmaf(logit, w_out[48], part);
            part += b_out[0];
        }

        #pragma unroll
        for (int off = 16; off > 0; off >>= 1)
            part += __shfl_down_sync(0xffffffffu, part, off);

        if (t == 0) {
            out[0] = 1.0f / (1.0f + expf(-part));
            g_cnt2 = 0;
        }
    }
}

extern "C" void kernel_launch(void* const* d_in, const int* in_sizes, int n_in,
                              void* d_out, int out_size) {
    const float* x     = (const float*)d_in[0];
    const float* emb   = (const float*)d_in[1];
    const float* w_log = (const float*)d_in[2];
    const float* b_log = (const float*)d_in[3];
    const float* w1    = (const float*)d_in[4];
    const float* b1    = (const float*)d_in[5];
    const float* w2    = (const float*)d_in[6];
    const float* b2    = (const float*)d_in[7];
    const float* w_out = (const float*)d_in[8];
    const float* b_out = (const float*)d_in[9];
    float* out = (float*)d_out;

    int F = in_sizes[0];                       // 2,000,000
    int tilef = (F + NTILES - 1) / NTILES;     // 4505

    const int s2_smem = 2 * CHUNK * 16 * 4 + 2 * CHUNK * 8;  // 36864 B
    static int configured = 0;
    if (!configured) {
        cudaFuncSetAttribute(stage2_kernel,
                             cudaFuncAttributeMaxDynamicSharedMemorySize, s2_smem);
        configured = 1;
    }

    stage1_kernel<<<NTILES * S1_SPLIT, S1_THREADS>>>(x, emb, F, tilef);
    stage2_kernel<<<NTILES, S2_THREADS, s2_smem>>>(x, emb, F, tilef,
                                                   w_log, b_log, w1, b1,
                                                   w2, b2, w_out, b_out, out);
}